// round 10
// baseline (speedup 1.0000x reference)
#include <cuda_runtime.h>
#include <cuda_fp16.h>
#include <cstdint>

// ---------------------------------------------------------------- constants
#define B_     64
#define T_     16
#define IMG_   84
#define FR_    7056         // 84*84
#define P_     7
#define NS_    144
#define K_     98
#define KP_    128          // physical row width (halves); logical K used = 112
#define KSTEPS 7            // 7 x k16 = 112 >= 98
#define E_     1024
#define NTOK_  1152
#define M_     73728

// Swizzled scratch: within each 128-half row, 16B chunk c lives at c ^ (row&7).
// Zero-init device globals; chunks never written stay zero (K tail padding).
__device__ __half g_A[(size_t)M_ * KP_];   // [m][128]  18.9 MB
__device__ __half g_B[(size_t)E_ * KP_];   // [e][128]  256 KB

// ---------------------------------------------------------------- helpers
__device__ __forceinline__ void mma_f16(float4& d, const uint32_t a[4],
                                        const uint32_t b[2]) {
    asm("mma.sync.aligned.m16n8k16.row.col.f32.f16.f16.f32 "
        "{%0,%1,%2,%3}, {%4,%5,%6,%7}, {%8,%9}, {%0,%1,%2,%3};"
        : "+f"(d.x), "+f"(d.y), "+f"(d.z), "+f"(d.w)
        : "r"(a[0]), "r"(a[1]), "r"(a[2]), "r"(a[3]), "r"(b[0]), "r"(b[1]));
}
__device__ __forceinline__ uint32_t smem_u32(const void* p) {
    uint32_t a;
    asm("{ .reg .u64 t; cvta.to.shared.u64 t, %1; cvt.u32.u64 %0, t; }"
        : "=r"(a) : "l"(p));
    return a;
}
#define MBAR_INIT(mb, c) \
    asm volatile("mbarrier.init.shared.b64 [%0], %1;" \
                 :: "r"((uint32_t)(mb)), "r"((uint32_t)(c)) : "memory")
#define MBAR_EXPECT_TX(mb, n) \
    asm volatile("mbarrier.arrive.expect_tx.shared.b64 _, [%0], %1;" \
                 :: "r"((uint32_t)(mb)), "r"((uint32_t)(n)) : "memory")
#define MBAR_WAIT(mb) do {                                                        \
    uint32_t _mb = (uint32_t)(mb); uint32_t _done;                                \
    asm volatile("{\n\t.reg .pred p;\n\t"                                         \
        "mbarrier.try_wait.parity.acquire.cta.shared::cta.b64 p, [%1], 0;\n\t"    \
        "selp.b32 %0, 1, 0, p;\n\t}" : "=r"(_done) : "r"(_mb) : "memory");        \
    if (!_done) {                                                                 \
        asm volatile("{\n\t.reg .pred P1;\n\t"                                    \
            "WL_%=:\n\t"                                                          \
            "mbarrier.try_wait.parity.acquire.cta.shared::cta.b64 P1, [%0], 0, 0x989680;\n\t" \
            "@P1 bra.uni WD_%=;\n\t"                                              \
            "bra.uni WL_%=;\n\t"                                                  \
            "WD_%=:\n\t}" :: "r"(_mb) : "memory");                                \
    }                                                                             \
} while (0)
__device__ __forceinline__ void bulk_g2s(uint32_t dst, const void* src,
                                         uint32_t bytes, uint32_t mbar) {
    asm volatile(
        "cp.async.bulk.shared::cta.global.mbarrier::complete_tx::bytes "
        "[%0], [%1], %2, [%3];"
        :: "r"(dst), "l"(src), "r"(bytes), "r"(mbar) : "memory");
}

// ---------------------------------------------------------------- prep
// block = (b, d): both tubelet frames in smem; one 16B chunk per work unit.
__global__ void gather_kernel(const float* __restrict__ video) {
    extern __shared__ float fr[];             // [2][7056]
    int bd = blockIdx.x;
    int b = bd >> 3, d = bd & 7;
    const float* src = video + (size_t)(b * T_ + d * 2) * FR_;
    for (int i = threadIdx.x; i < 2 * FR_; i += blockDim.x) fr[i] = src[i];
    __syncthreads();

    int mbase = b * NTOK_ + d * NS_;
    for (int u = threadIdx.x; u < NS_ * 13; u += blockDim.x) {
        int s = u / 13, c = u - s * 13;       // chunk c covers kk = 8c..8c+7
        int h = s / 12, w = s - h * 12;
        const float* f0 = fr + h * (P_ * IMG_) + w * P_;
        __half hv[8];
#pragma unroll
        for (int j = 0; j < 8; ++j) {
            int kk = c * 8 + j;
            float v = 0.f;
            if (kk < K_) {
                int ts = kk >= 49;
                int k  = kk - ts * 49;
                int pi = k / P_, pj = k - pi * P_;
                v = f0[ts * FR_ + pi * IMG_ + pj];
            }
            hv[j] = __float2half_rn(v);
        }
        int ph = c ^ (s & 7);                 // (mbase+s)&7 == s&7
        *(uint4*)(&g_A[(size_t)(mbase + s) * KP_ + ph * 8]) = *(const uint4*)hv;
    }
}

__global__ void wk_kernel(const float* __restrict__ W) {
    int idx = blockIdx.x * blockDim.x + threadIdx.x;
    if (idx >= E_ * K_) return;
    int e = idx / K_, k = idx - e * K_;
    int ph = (((k >> 3) ^ (e & 7)) << 3) | (k & 7);
    g_B[(size_t)e * KP_ + ph] = __float2half_rn(W[idx]);
}

// ---------------------------------------------------------------- GEMM
// CTA 256(m) x 128(e), 8 warps of 64x64, full-K resident (bulk-staged,
// swizzled). Per warp: 2 n-halves; pos/bias register-prefetched so the
// epilogue has zero load latency; prefetch rides under the MMA stream.
#define MT   256
#define ET   128
#define SAB  (MT * KP_)             // halves in A tile (64 KB)
#define SBB  (ET * KP_)             // halves in B tile (32 KB)
#define SMEM_BYTES ((SAB + SBB) * 2)   // 98304 B

__global__ __launch_bounds__(256, 1)
void gemm_kernel(const float* __restrict__ bias,
                 const float* __restrict__ pos,
                 float* __restrict__ out) {
    extern __shared__ __half sm[];
    __half* sA = sm;                  // [256][128] swizzled rows
    __half* sB = sm + SAB;            // [128][128]
    __shared__ __align__(8) unsigned long long bars[5];

    const int tid  = threadIdx.x;
    const int lane = tid & 31;
    const int wid  = tid >> 5;
    const int grp  = lane >> 2;        // 0..7
    const int tg   = lane & 3;         // 0..3
    const int wm   = wid & 3;          // m-quarter -> wm*64
    const int wn   = wid >> 2;         // e-half    -> wn*64

    const int e0 = blockIdx.x * ET;
    const int m0 = blockIdx.y * MT;

    const uint32_t barB = smem_u32(&bars[0]);
    const uint32_t barA = smem_u32(&bars[1]);   // +8*q for quarter q

    if (tid == 0) {
#pragma unroll
        for (int q = 0; q < 5; ++q) MBAR_INIT(smem_u32(&bars[q]), 1);
    }
    __syncthreads();

    if (tid == 0) {
        MBAR_EXPECT_TX(barB, SBB * 2);
        bulk_g2s(smem_u32(sB), g_B + (size_t)e0 * KP_, SBB * 2, barB);
#pragma unroll
        for (int q = 0; q < 4; ++q) {
            MBAR_EXPECT_TX(barA + q * 8, 64 * KP_ * 2);
            bulk_g2s(smem_u32(sA) + q * 64 * KP_ * 2,
                     g_A + (size_t)(m0 + q * 64) * KP_,
                     64 * KP_ * 2, barA + q * 8);
        }
    }

    // epilogue coordinates
    const int n0 = m0 % NTOK_;
    int mg[4], ng0[4], ng1[4];
#pragma unroll
    for (int mf = 0; mf < 4; ++mf) {
        int rl = wm * 64 + mf * 16 + grp;
        mg[mf] = m0 + rl;
        int n  = n0 + rl;      if (n  >= NTOK_) n  -= NTOK_;
        int n2 = n0 + rl + 8;  if (n2 >= NTOK_) n2 -= NTOK_;
        ng0[mf] = n; ng1[mf] = n2;
    }

    float2 pp0[4][4], pp1[4][4], bb[4];
    auto prefetch = [&](int nb) {
        const int colb = e0 + wn * 64 + nb * 32 + tg * 2;
#pragma unroll
        for (int nf = 0; nf < 4; ++nf)
            bb[nf] = *(const float2*)(bias + colb + nf * 8);
#pragma unroll
        for (int mf = 0; mf < 4; ++mf) {
            const float* pr0 = pos + (size_t)ng0[mf] * E_ + colb;
            const float* pr1 = pos + (size_t)ng1[mf] * E_ + colb;
#pragma unroll
            for (int nf = 0; nf < 4; ++nf) {
                pp0[mf][nf] = *(const float2*)(pr0 + nf * 8);
                pp1[mf][nf] = *(const float2*)(pr1 + nf * 8);
            }
        }
    };

    MBAR_WAIT(barB);
    MBAR_WAIT(barA + wm * 8);          // each warp needs only its A quarter

    const __half* wA = sA + (wm * 64 + grp) * KP_;
    const __half* wB = sB + (wn * 64 + grp) * KP_;

#pragma unroll
    for (int half = 0; half < 2; ++half) {
        const int nb = half * 4;

        prefetch(half);                // loads hidden under the MMA loop below

        float4 acc[4][4];
#pragma unroll
        for (int i = 0; i < 4; ++i)
#pragma unroll
            for (int j = 0; j < 4; ++j) acc[i][j] = make_float4(0.f, 0.f, 0.f, 0.f);

#pragma unroll
        for (int ks = 0; ks < KSTEPS; ++ks) {
            const int off0 = (((2 * ks)     ^ grp) << 3) + tg * 2;
            const int off1 = (((2 * ks + 1) ^ grp) << 3) + tg * 2;

            uint32_t af[4][4], bf[4][2];
#pragma unroll
            for (int mf = 0; mf < 4; ++mf) {
                const __half* r0 = wA + mf * 16 * KP_;
                af[mf][0] = *(const uint32_t*)(r0 + off0);
                af[mf][1] = *(const uint32_t*)(r0 + 8 * KP_ + off0);
                af[mf][2] = *(const uint32_t*)(r0 + off1);
                af[mf][3] = *(const uint32_t*)(r0 + 8 * KP_ + off1);
            }
#pragma unroll
            for (int nf = 0; nf < 4; ++nf) {
                const __half* r0 = wB + (nb + nf) * 8 * KP_;
                bf[nf][0] = *(const uint32_t*)(r0 + off0);
                bf[nf][1] = *(const uint32_t*)(r0 + off1);
            }
#pragma unroll
            for (int mf = 0; mf < 4; ++mf)
#pragma unroll
                for (int nf = 0; nf < 4; ++nf)
                    mma_f16(acc[mf][nf], af[mf], bf[nf]);
        }

        // epilogue: pure FADD + STG (operands already in registers)
        const int colb = e0 + wn * 64 + nb * 8 + tg * 2;
#pragma unroll
        for (int mf = 0; mf < 4; ++mf) {
            float* or0 = out + (size_t)mg[mf] * E_ + colb;
            float* or1 = or0 + 8 * E_;
#pragma unroll
            for (int nf = 0; nf < 4; ++nf) {
                float4 a  = acc[mf][nf];
                float2 o0 = make_float2(a.x + bb[nf].x + pp0[mf][nf].x,
                                        a.y + bb[nf].y + pp0[mf][nf].y);
                float2 o1 = make_float2(a.z + bb[nf].x + pp1[mf][nf].x,
                                        a.w + bb[nf].y + pp1[mf][nf].y);
                __stcs((float2*)(or0 + nf * 8), o0);
                __stcs((float2*)(or1 + nf * 8), o1);
            }
        }
    }
}

// ---------------------------------------------------------------- launch
extern "C" void kernel_launch(void* const* d_in, const int* in_sizes, int n_in,
                              void* d_out, int out_size) {
    const float* video = (const float*)d_in[0];   // [64,16,1,84,84]
    const float* W     = (const float*)d_in[1];   // [1024,98]
    const float* bias  = (const float*)d_in[2];   // [1024]
    const float* pos   = (const float*)d_in[3];   // [1,1152,1024]
    float* out         = (float*)d_out;           // [64,1152,1024]

    cudaFuncSetAttribute(gemm_kernel, cudaFuncAttributeMaxDynamicSharedMemorySize,
                         SMEM_BYTES);
    cudaFuncSetAttribute(gather_kernel, cudaFuncAttributeMaxDynamicSharedMemorySize,
                         2 * FR_ * 4);

    gather_kernel<<<B_ * 8, 256, 2 * FR_ * 4>>>(video);
    wk_kernel<<<(E_ * K_ + 255) / 256, 256>>>(W);
    gemm_kernel<<<dim3(E_ / ET, M_ / MT), 256, SMEM_BYTES>>>(bias, pos, out);
}

// round 11
// speedup vs baseline: 1.0149x; 1.0149x over previous
#include <cuda_runtime.h>
#include <cuda_fp16.h>
#include <cstdint>

// ---------------------------------------------------------------- constants
#define B_     64
#define T_     16
#define IMG_   84
#define FR_    7056         // 84*84
#define P_     7
#define NS_    144
#define K_     98
#define KP_    128          // physical row width (halves)
#define KSTEPS 6            // tensor path: 6 x k16 = 96; k=96,97 via FFMA
#define E_     1024
#define NTOK_  1152
#define M_     73728

// Swizzled scratch: within each 128-half row, 16B chunk c lives at c ^ (row&7).
// Zero-init device globals; chunk 12 halves [98,104) written as zero by gather,
// never written by wk (stays zero).
__device__ __half g_A[(size_t)M_ * KP_];   // [m][128]  18.9 MB
__device__ __half g_B[(size_t)E_ * KP_];   // [e][128]  256 KB

// ---------------------------------------------------------------- helpers
__device__ __forceinline__ void mma_f16(float4& d, const uint32_t a[4],
                                        const uint32_t b[2]) {
    asm("mma.sync.aligned.m16n8k16.row.col.f32.f16.f16.f32 "
        "{%0,%1,%2,%3}, {%4,%5,%6,%7}, {%8,%9}, {%0,%1,%2,%3};"
        : "+f"(d.x), "+f"(d.y), "+f"(d.z), "+f"(d.w)
        : "r"(a[0]), "r"(a[1]), "r"(a[2]), "r"(a[3]), "r"(b[0]), "r"(b[1]));
}
__device__ __forceinline__ uint32_t smem_u32(const void* p) {
    uint32_t a;
    asm("{ .reg .u64 t; cvta.to.shared.u64 t, %1; cvt.u32.u64 %0, t; }"
        : "=r"(a) : "l"(p));
    return a;
}
#define MBAR_INIT(mb, c) \
    asm volatile("mbarrier.init.shared.b64 [%0], %1;" \
                 :: "r"((uint32_t)(mb)), "r"((uint32_t)(c)) : "memory")
#define MBAR_EXPECT_TX(mb, n) \
    asm volatile("mbarrier.arrive.expect_tx.shared.b64 _, [%0], %1;" \
                 :: "r"((uint32_t)(mb)), "r"((uint32_t)(n)) : "memory")
#define MBAR_WAIT(mb) do {                                                        \
    uint32_t _mb = (uint32_t)(mb); uint32_t _done;                                \
    asm volatile("{\n\t.reg .pred p;\n\t"                                         \
        "mbarrier.try_wait.parity.acquire.cta.shared::cta.b64 p, [%1], 0;\n\t"    \
        "selp.b32 %0, 1, 0, p;\n\t}" : "=r"(_done) : "r"(_mb) : "memory");        \
    if (!_done) {                                                                 \
        asm volatile("{\n\t.reg .pred P1;\n\t"                                    \
            "WL_%=:\n\t"                                                          \
            "mbarrier.try_wait.parity.acquire.cta.shared::cta.b64 P1, [%0], 0, 0x989680;\n\t" \
            "@P1 bra.uni WD_%=;\n\t"                                              \
            "bra.uni WL_%=;\n\t"                                                  \
            "WD_%=:\n\t}" :: "r"(_mb) : "memory");                                \
    }                                                                             \
} while (0)
__device__ __forceinline__ void bulk_g2s(uint32_t dst, const void* src,
                                         uint32_t bytes, uint32_t mbar) {
    asm volatile(
        "cp.async.bulk.shared::cta.global.mbarrier::complete_tx::bytes "
        "[%0], [%1], %2, [%3];"
        :: "r"(dst), "l"(src), "r"(bytes), "r"(mbar) : "memory");
}

// ---------------------------------------------------------------- prep
// block = (b, d). Both tubelet frames cached in smem as fp16 (28 KB) so
// occupancy stays thread-limited. One 16B chunk of g_A per work unit.
__global__ void gather_kernel(const float* __restrict__ video) {
    extern __shared__ __half fr[];            // [2*7056] halves
    int bd = blockIdx.x;
    int b = bd >> 3, d = bd & 7;
    const float* src = video + (size_t)(b * T_ + d * 2) * FR_;
    for (int i = threadIdx.x; i < (2 * FR_) / 4; i += blockDim.x) {
        float4 v = *(const float4*)(src + i * 4);
        __half h[4] = {__float2half_rn(v.x), __float2half_rn(v.y),
                       __float2half_rn(v.z), __float2half_rn(v.w)};
        *(uint2*)(&fr[i * 4]) = *(const uint2*)h;
    }
    __syncthreads();

    int mbase = b * NTOK_ + d * NS_;
    for (int u = threadIdx.x; u < NS_ * 13; u += blockDim.x) {
        int s = u / 13, c = u - s * 13;       // chunk c covers kk = 8c..8c+7
        int h = s / 12, w = s - h * 12;
        const __half* f0 = fr + h * (P_ * IMG_) + w * P_;
        __half hv[8];
#pragma unroll
        for (int j = 0; j < 8; ++j) {
            int kk = c * 8 + j;
            __half v = __ushort_as_half((unsigned short)0);
            if (kk < K_) {
                int ts = kk >= 49;
                int k  = kk - ts * 49;
                int pi = k / P_, pj = k - pi * P_;
                v = f0[ts * FR_ + pi * IMG_ + pj];
            }
            hv[j] = v;
        }
        int ph = c ^ (s & 7);                 // (mbase+s)&7 == s&7
        *(uint4*)(&g_A[(size_t)(mbase + s) * KP_ + ph * 8]) = *(const uint4*)hv;
    }
}

__global__ void wk_kernel(const float* __restrict__ W) {
    int idx = blockIdx.x * blockDim.x + threadIdx.x;
    if (idx >= E_ * K_) return;
    int e = idx / K_, k = idx - e * K_;
    int ph = (((k >> 3) ^ (e & 7)) << 3) | (k & 7);
    g_B[(size_t)e * KP_ + ph] = __float2half_rn(W[idx]);
}

// ---------------------------------------------------------------- GEMM
// CTA 256(m) x 128(e), 8 warps of 64x64, full-K resident (bulk-staged,
// swizzled). Tensor path: 6 k16-steps (k<96). k=96,97 folded in via FFMA
// on the otherwise-idle fp32 pipe. Two n-halves per warp, epilogue after
// each half so tensor/memory work interleaves across warps.
#define MT   256
#define ET   128
#define SAB  (MT * KP_)             // halves in A tile (64 KB)
#define SBB  (ET * KP_)             // halves in B tile (32 KB)
#define SMEM_BYTES ((SAB + SBB) * 2)   // 98304 B

__global__ __launch_bounds__(256, 1)
void gemm_kernel(const float* __restrict__ bias,
                 const float* __restrict__ pos,
                 float* __restrict__ out) {
    extern __shared__ __half sm[];
    __half* sA = sm;                  // [256][128] swizzled rows
    __half* sB = sm + SAB;            // [128][128]
    __shared__ __align__(8) unsigned long long bars[5];

    const int tid  = threadIdx.x;
    const int lane = tid & 31;
    const int wid  = tid >> 5;
    const int grp  = lane >> 2;        // 0..7
    const int tg   = lane & 3;         // 0..3
    const int wm   = wid & 3;          // m-quarter -> wm*64
    const int wn   = wid >> 2;         // e-half    -> wn*64

    const int e0 = blockIdx.x * ET;
    const int m0 = blockIdx.y * MT;

    const uint32_t barB = smem_u32(&bars[0]);
    const uint32_t barA = smem_u32(&bars[1]);   // +8*q for quarter q

    if (tid == 0) {
#pragma unroll
        for (int q = 0; q < 5; ++q) MBAR_INIT(smem_u32(&bars[q]), 1);
    }
    __syncthreads();

    if (tid == 0) {
        MBAR_EXPECT_TX(barB, SBB * 2);
        bulk_g2s(smem_u32(sB), g_B + (size_t)e0 * KP_, SBB * 2, barB);
#pragma unroll
        for (int q = 0; q < 4; ++q) {
            MBAR_EXPECT_TX(barA + q * 8, 64 * KP_ * 2);
            bulk_g2s(smem_u32(sA) + q * 64 * KP_ * 2,
                     g_A + (size_t)(m0 + q * 64) * KP_,
                     64 * KP_ * 2, barA + q * 8);
        }
    }

    // epilogue coordinates
    const int n0 = m0 % NTOK_;
    int mg[4], ng0[4], ng1[4];
#pragma unroll
    for (int mf = 0; mf < 4; ++mf) {
        int rl = wm * 64 + mf * 16 + grp;
        mg[mf] = m0 + rl;
        int n  = n0 + rl;      if (n  >= NTOK_) n  -= NTOK_;
        int n2 = n0 + rl + 8;  if (n2 >= NTOK_) n2 -= NTOK_;
        ng0[mf] = n; ng1[mf] = n2;
    }

    MBAR_WAIT(barB);
    MBAR_WAIT(barA + wm * 8);          // each warp needs only its A quarter

    const __half* wA = sA + (wm * 64 + grp) * KP_;
    const __half* wB = sB + (wn * 64 + grp) * KP_;

    // A operands for the k=96,97 FFMA correction (chunk 12; same for both halves)
    float2 ca0[4], ca1[4];
    {
        const int ca = (12 ^ grp) << 3;        // halves offset within row
#pragma unroll
        for (int mf = 0; mf < 4; ++mf) {
            ca0[mf] = __half22float2(*(const __half2*)(wA + mf * 16 * KP_ + ca));
            ca1[mf] = __half22float2(*(const __half2*)(wA + (mf * 16 + 8) * KP_ + ca));
        }
    }

#pragma unroll
    for (int half = 0; half < 2; ++half) {
        const int nb = half * 4;                 // nf block base (4 per half)
        float4 acc[4][4];
#pragma unroll
        for (int i = 0; i < 4; ++i)
#pragma unroll
            for (int j = 0; j < 4; ++j) acc[i][j] = make_float4(0.f, 0.f, 0.f, 0.f);

#pragma unroll
        for (int ks = 0; ks < KSTEPS; ++ks) {
            const int off0 = (((2 * ks)     ^ grp) << 3) + tg * 2;
            const int off1 = (((2 * ks + 1) ^ grp) << 3) + tg * 2;

            uint32_t af[4][4], bf[4][2];
#pragma unroll
            for (int mf = 0; mf < 4; ++mf) {
                const __half* r0 = wA + mf * 16 * KP_;
                af[mf][0] = *(const uint32_t*)(r0 + off0);
                af[mf][1] = *(const uint32_t*)(r0 + 8 * KP_ + off0);
                af[mf][2] = *(const uint32_t*)(r0 + off1);
                af[mf][3] = *(const uint32_t*)(r0 + 8 * KP_ + off1);
            }
#pragma unroll
            for (int nf = 0; nf < 4; ++nf) {
                const __half* r0 = wB + (nb + nf) * 8 * KP_;
                bf[nf][0] = *(const uint32_t*)(r0 + off0);
                bf[nf][1] = *(const uint32_t*)(r0 + off1);
            }
#pragma unroll
            for (int mf = 0; mf < 4; ++mf)
#pragma unroll
                for (int nf = 0; nf < 4; ++nf)
                    mma_f16(acc[mf][nf], af[mf], bf[nf]);
        }

        // FFMA correction: kk = 96,97 (fp32 pipe; tensor pipe idle elsewhere)
#pragma unroll
        for (int nf = 0; nf < 4; ++nf) {
            int er = wn * 64 + (nb + nf) * 8 + 2 * tg;     // global e - e0
            const __half* bp0 = sB + (size_t)er * KP_ + ((12 ^ (er & 7)) << 3);
            const __half* bp1 = sB + (size_t)(er + 1) * KP_ + ((12 ^ ((er + 1) & 7)) << 3);
            float2 b0 = __half22float2(*(const __half2*)bp0);
            float2 b1 = __half22float2(*(const __half2*)bp1);
#pragma unroll
            for (int mf = 0; mf < 4; ++mf) {
                float4& a = acc[mf][nf];
                a.x += ca0[mf].x * b0.x + ca0[mf].y * b0.y;
                a.y += ca0[mf].x * b1.x + ca0[mf].y * b1.y;
                a.z += ca1[mf].x * b0.x + ca1[mf].y * b0.y;
                a.w += ca1[mf].x * b1.x + ca1[mf].y * b1.y;
            }
        }

        // epilogue for this n-half: out = acc + bias + pos
        const int colb = e0 + wn * 64 + nb * 8 + tg * 2;
#pragma unroll
        for (int mf = 0; mf < 4; ++mf) {
            const float* pr0 = pos + (size_t)ng0[mf] * E_ + colb;
            const float* pr1 = pos + (size_t)ng1[mf] * E_ + colb;
            float* or0 = out + (size_t)mg[mf] * E_ + colb;
            float* or1 = or0 + 8 * E_;
#pragma unroll
            for (int nf = 0; nf < 4; ++nf) {
                float2 bb = *(const float2*)(bias + colb + nf * 8);
                float2 p0 = *(const float2*)(pr0 + nf * 8);
                float2 p1 = *(const float2*)(pr1 + nf * 8);
                float4 a  = acc[mf][nf];
                float2 o0 = make_float2(a.x + bb.x + p0.x, a.y + bb.y + p0.y);
                float2 o1 = make_float2(a.z + bb.x + p1.x, a.w + bb.y + p1.y);
                __stcs((float2*)(or0 + nf * 8), o0);
                __stcs((float2*)(or1 + nf * 8), o1);
            }
        }
    }
}

// ---------------------------------------------------------------- launch
extern "C" void kernel_launch(void* const* d_in, const int* in_sizes, int n_in,
                              void* d_out, int out_size) {
    const float* video = (const float*)d_in[0];   // [64,16,1,84,84]
    const float* W     = (const float*)d_in[1];   // [1024,98]
    const float* bias  = (const float*)d_in[2];   // [1024]
    const float* pos   = (const float*)d_in[3];   // [1,1152,1024]
    float* out         = (float*)d_out;           // [64,1152,1024]

    cudaFuncSetAttribute(gemm_kernel, cudaFuncAttributeMaxDynamicSharedMemorySize,
                         SMEM_BYTES);
    cudaFuncSetAttribute(gather_kernel, cudaFuncAttributeMaxDynamicSharedMemorySize,
                         2 * FR_ * 2);

    gather_kernel<<<B_ * 8, 256, 2 * FR_ * 2>>>(video);
    wk_kernel<<<(E_ * K_ + 255) / 256, 256>>>(W);
    gemm_kernel<<<dim3(E_ / ET, M_ / MT), 256, SMEM_BYTES>>>(bias, pos, out);
}

// round 12
// speedup vs baseline: 1.1242x; 1.1077x over previous
#include <cuda_runtime.h>
#include <cuda_fp16.h>
#include <cstdint>

// ---------------------------------------------------------------- constants
#define B_     64
#define T_     16
#define IMG_   84
#define FR_    7056         // 84*84
#define P_     7
#define NS_    144
#define K_     98
#define KP_    128          // physical row width (halves)
#define KSTEPS 6            // tensor path: 6 x k16 = 96; k=96,97 via FFMA
#define E_     1024
#define NTOK_  1152
#define M_     73728

// Swizzled scratch: within each 128-half row, 16B chunk c lives at c ^ (row&7).
__device__ __half g_A[(size_t)M_ * KP_];   // [m][128]  18.9 MB
__device__ __half g_B[(size_t)E_ * KP_];   // [e][128]  256 KB

// ---------------------------------------------------------------- helpers
__device__ __forceinline__ void mma_f16(float4& d, const uint32_t a[4],
                                        const uint32_t b[2]) {
    asm("mma.sync.aligned.m16n8k16.row.col.f32.f16.f16.f32 "
        "{%0,%1,%2,%3}, {%4,%5,%6,%7}, {%8,%9}, {%0,%1,%2,%3};"
        : "+f"(d.x), "+f"(d.y), "+f"(d.z), "+f"(d.w)
        : "r"(a[0]), "r"(a[1]), "r"(a[2]), "r"(a[3]), "r"(b[0]), "r"(b[1]));
}
__device__ __forceinline__ uint32_t smem_u32(const void* p) {
    uint32_t a;
    asm("{ .reg .u64 t; cvta.to.shared.u64 t, %1; cvt.u32.u64 %0, t; }"
        : "=r"(a) : "l"(p));
    return a;
}
#define MBAR_INIT(mb, c) \
    asm volatile("mbarrier.init.shared.b64 [%0], %1;" \
                 :: "r"((uint32_t)(mb)), "r"((uint32_t)(c)) : "memory")
#define MBAR_EXPECT_TX(mb, n) \
    asm volatile("mbarrier.arrive.expect_tx.shared.b64 _, [%0], %1;" \
                 :: "r"((uint32_t)(mb)), "r"((uint32_t)(n)) : "memory")
#define MBAR_WAIT(mb, ph) do {                                                    \
    uint32_t _mb = (uint32_t)(mb); uint32_t _ph = (uint32_t)(ph); uint32_t _done; \
    asm volatile("{\n\t.reg .pred p;\n\t"                                         \
        "mbarrier.try_wait.parity.acquire.cta.shared::cta.b64 p, [%1], %2;\n\t"   \
        "selp.b32 %0, 1, 0, p;\n\t}" : "=r"(_done) : "r"(_mb), "r"(_ph) : "memory"); \
    if (!_done) {                                                                 \
        asm volatile("{\n\t.reg .pred P1;\n\t"                                    \
            "WL_%=:\n\t"                                                          \
            "mbarrier.try_wait.parity.acquire.cta.shared::cta.b64 P1, [%0], %1, 0x989680;\n\t" \
            "@P1 bra.uni WD_%=;\n\t"                                              \
            "bra.uni WL_%=;\n\t"                                                  \
            "WD_%=:\n\t}" :: "r"(_mb), "r"(_ph) : "memory");                      \
    }                                                                             \
} while (0)
__device__ __forceinline__ void bulk_g2s(uint32_t dst, const void* src,
                                         uint32_t bytes, uint32_t mbar) {
    asm volatile(
        "cp.async.bulk.shared::cta.global.mbarrier::complete_tx::bytes "
        "[%0], [%1], %2, [%3];"
        :: "r"(dst), "l"(src), "r"(bytes), "r"(mbar) : "memory");
}

// ---------------------------------------------------------------- prep
__global__ void gather_kernel(const float* __restrict__ video) {
    extern __shared__ __half fr[];            // [2*7056] halves
    int bd = blockIdx.x;
    int b = bd >> 3, d = bd & 7;
    const float* src = video + (size_t)(b * T_ + d * 2) * FR_;
    for (int i = threadIdx.x; i < (2 * FR_) / 4; i += blockDim.x) {
        float4 v = *(const float4*)(src + i * 4);
        __half h[4] = {__float2half_rn(v.x), __float2half_rn(v.y),
                       __float2half_rn(v.z), __float2half_rn(v.w)};
        *(uint2*)(&fr[i * 4]) = *(const uint2*)h;
    }
    __syncthreads();

    int mbase = b * NTOK_ + d * NS_;
    for (int u = threadIdx.x; u < NS_ * 13; u += blockDim.x) {
        int s = u / 13, c = u - s * 13;       // chunk c covers kk = 8c..8c+7
        int h = s / 12, w = s - h * 12;
        const __half* f0 = fr + h * (P_ * IMG_) + w * P_;
        __half hv[8];
#pragma unroll
        for (int j = 0; j < 8; ++j) {
            int kk = c * 8 + j;
            __half v = __ushort_as_half((unsigned short)0);
            if (kk < K_) {
                int ts = kk >= 49;
                int k  = kk - ts * 49;
                int pi = k / P_, pj = k - pi * P_;
                v = f0[ts * FR_ + pi * IMG_ + pj];
            }
            hv[j] = v;
        }
        int ph = c ^ (s & 7);                 // (mbase+s)&7 == s&7
        *(uint4*)(&g_A[(size_t)(mbase + s) * KP_ + ph * 8]) = *(const uint4*)hv;
    }
}

__global__ void wk_kernel(const float* __restrict__ W) {
    int idx = blockIdx.x * blockDim.x + threadIdx.x;
    if (idx >= E_ * K_) return;
    int e = idx / K_, k = idx - e * K_;
    int ph = (((k >> 3) ^ (e & 7)) << 3) | (k & 7);
    g_B[(size_t)e * KP_ + ph] = __float2half_rn(W[idx]);
}

// ---------------------------------------------------------------- GEMM
// Persistent-strip GEMM: grid 8(e) x 18(strips). Each CTA fixes e0, loads B
// once, then pipelines 16 m-tiles of 256x128 with double-buffered bulk-copied
// A (prefetch distance 2). Tensor path K=96 + FFMA tail (k=96,97).
#define MT      256
#define ET      128
#define TILES   16          // m-tiles per CTA
#define SBB     (ET * KP_)              // B halves (32 KB)
#define SAB     (MT * KP_)              // A halves per buffer (64 KB)
#define ATILE_BYTES (SAB * 2)           // 65536
#define SMEM_BYTES ((SBB + 2 * SAB) * 2)   // 163840 B

__global__ __launch_bounds__(256, 1)
void gemm_kernel(const float* __restrict__ bias,
                 const float* __restrict__ pos,
                 float* __restrict__ out) {
    extern __shared__ __half sm[];
    __half* sB = sm;                   // [128][128] swizzled rows
    __half* sA0 = sm + SBB;            // buffer 0
    __half* sA1 = sA0 + SAB;           // buffer 1
    __shared__ __align__(8) unsigned long long bars[3];  // B, A0, A1

    const int tid  = threadIdx.x;
    const int lane = tid & 31;
    const int wid  = tid >> 5;
    const int grp  = lane >> 2;        // 0..7
    const int tg   = lane & 3;         // 0..3
    const int wm   = wid & 3;          // m-quarter -> wm*64
    const int wn   = wid >> 2;         // e-half    -> wn*64

    const int e0 = blockIdx.x * ET;
    const int j0 = blockIdx.y * TILES; // first m-tile index

    const uint32_t barB  = smem_u32(&bars[0]);
    const uint32_t barA0 = smem_u32(&bars[1]);
    const uint32_t barA1 = smem_u32(&bars[2]);

    if (tid == 0) {
        MBAR_INIT(barB, 1);
        MBAR_INIT(barA0, 1);
        MBAR_INIT(barA1, 1);
    }
    __syncthreads();

    if (tid == 0) {
        MBAR_EXPECT_TX(barB, SBB * 2);
        bulk_g2s(smem_u32(sB), g_B + (size_t)e0 * KP_, SBB * 2, barB);
        MBAR_EXPECT_TX(barA0, ATILE_BYTES);
        bulk_g2s(smem_u32(sA0), g_A + (size_t)j0 * MT * KP_, ATILE_BYTES, barA0);
        MBAR_EXPECT_TX(barA1, ATILE_BYTES);
        bulk_g2s(smem_u32(sA1), g_A + (size_t)(j0 + 1) * MT * KP_, ATILE_BYTES, barA1);
    }

    MBAR_WAIT(barB, 0);
    const __half* wB = sB + (wn * 64 + grp) * KP_;

#pragma unroll 1
    for (int i = 0; i < TILES; ++i) {
        const int buf = i & 1;
        const uint32_t barA = buf ? barA1 : barA0;
        __half* sA = buf ? sA1 : sA0;
        MBAR_WAIT(barA, (i >> 1) & 1);

        const int m0 = (j0 + i) * MT;
        const __half* wA = sA + (wm * 64 + grp) * KP_;

        // epilogue coordinates for this tile
        const int n0 = m0 % NTOK_;
        int mg[4], ng0[4], ng1[4];
#pragma unroll
        for (int mf = 0; mf < 4; ++mf) {
            int rl = wm * 64 + mf * 16 + grp;
            mg[mf] = m0 + rl;
            int n  = n0 + rl;      if (n  >= NTOK_) n  -= NTOK_;
            int n2 = n0 + rl + 8;  if (n2 >= NTOK_) n2 -= NTOK_;
            ng0[mf] = n; ng1[mf] = n2;
        }

        // A operands for the k=96,97 FFMA tail (chunk 12)
        float2 ca0[4], ca1[4];
        {
            const int ca = (12 ^ grp) << 3;
#pragma unroll
            for (int mf = 0; mf < 4; ++mf) {
                ca0[mf] = __half22float2(*(const __half2*)(wA + mf * 16 * KP_ + ca));
                ca1[mf] = __half22float2(*(const __half2*)(wA + (mf * 16 + 8) * KP_ + ca));
            }
        }

#pragma unroll
        for (int half = 0; half < 2; ++half) {
            const int nb = half * 4;
            float4 acc[4][4];
#pragma unroll
            for (int a = 0; a < 4; ++a)
#pragma unroll
                for (int b = 0; b < 4; ++b) acc[a][b] = make_float4(0.f, 0.f, 0.f, 0.f);

#pragma unroll
            for (int ks = 0; ks < KSTEPS; ++ks) {
                const int off0 = (((2 * ks)     ^ grp) << 3) + tg * 2;
                const int off1 = (((2 * ks + 1) ^ grp) << 3) + tg * 2;

                uint32_t af[4][4], bf[4][2];
#pragma unroll
                for (int mf = 0; mf < 4; ++mf) {
                    const __half* r0 = wA + mf * 16 * KP_;
                    af[mf][0] = *(const uint32_t*)(r0 + off0);
                    af[mf][1] = *(const uint32_t*)(r0 + 8 * KP_ + off0);
                    af[mf][2] = *(const uint32_t*)(r0 + off1);
                    af[mf][3] = *(const uint32_t*)(r0 + 8 * KP_ + off1);
                }
#pragma unroll
                for (int nf = 0; nf < 4; ++nf) {
                    const __half* r0 = wB + (nb + nf) * 8 * KP_;
                    bf[nf][0] = *(const uint32_t*)(r0 + off0);
                    bf[nf][1] = *(const uint32_t*)(r0 + off1);
                }
#pragma unroll
                for (int mf = 0; mf < 4; ++mf)
#pragma unroll
                    for (int nf = 0; nf < 4; ++nf)
                        mma_f16(acc[mf][nf], af[mf], bf[nf]);
            }

            // FFMA tail: kk = 96,97 on the fp32 pipe
#pragma unroll
            for (int nf = 0; nf < 4; ++nf) {
                int er = wn * 64 + (nb + nf) * 8 + 2 * tg;
                const __half* bp0 = sB + (size_t)er * KP_ + ((12 ^ (er & 7)) << 3);
                const __half* bp1 = sB + (size_t)(er + 1) * KP_ + ((12 ^ ((er + 1) & 7)) << 3);
                float2 b0 = __half22float2(*(const __half2*)bp0);
                float2 b1 = __half22float2(*(const __half2*)bp1);
#pragma unroll
                for (int mf = 0; mf < 4; ++mf) {
                    float4& a = acc[mf][nf];
                    a.x += ca0[mf].x * b0.x + ca0[mf].y * b0.y;
                    a.y += ca0[mf].x * b1.x + ca0[mf].y * b1.y;
                    a.z += ca1[mf].x * b0.x + ca1[mf].y * b0.y;
                    a.w += ca1[mf].x * b1.x + ca1[mf].y * b1.y;
                }
            }

            // epilogue: out = acc + bias + pos
            const int colb = e0 + wn * 64 + nb * 8 + tg * 2;
#pragma unroll
            for (int mf = 0; mf < 4; ++mf) {
                const float* pr0 = pos + (size_t)ng0[mf] * E_ + colb;
                const float* pr1 = pos + (size_t)ng1[mf] * E_ + colb;
                float* or0 = out + (size_t)mg[mf] * E_ + colb;
                float* or1 = or0 + 8 * E_;
#pragma unroll
                for (int nf = 0; nf < 4; ++nf) {
                    float2 bb = *(const float2*)(bias + colb + nf * 8);
                    float2 p0 = *(const float2*)(pr0 + nf * 8);
                    float2 p1 = *(const float2*)(pr1 + nf * 8);
                    float4 a  = acc[mf][nf];
                    float2 o0 = make_float2(a.x + bb.x + p0.x, a.y + bb.y + p0.y);
                    float2 o1 = make_float2(a.z + bb.x + p1.x, a.w + bb.y + p1.y);
                    __stcs((float2*)(or0 + nf * 8), o0);
                    __stcs((float2*)(or1 + nf * 8), o1);
                }
            }
        }

        // all warps finished reading buffer `buf` -> refill it 2 tiles ahead
        __syncthreads();
        if (tid == 0 && i + 2 < TILES) {
            MBAR_EXPECT_TX(barA, ATILE_BYTES);
            bulk_g2s(smem_u32(sA), g_A + (size_t)(j0 + i + 2) * MT * KP_,
                     ATILE_BYTES, barA);
        }
    }
}

// ---------------------------------------------------------------- launch
extern "C" void kernel_launch(void* const* d_in, const int* in_sizes, int n_in,
                              void* d_out, int out_size) {
    const float* video = (const float*)d_in[0];   // [64,16,1,84,84]
    const float* W     = (const float*)d_in[1];   // [1024,98]
    const float* bias  = (const float*)d_in[2];   // [1024]
    const float* pos   = (const float*)d_in[3];   // [1,1152,1024]
    float* out         = (float*)d_out;           // [64,1152,1024]

    cudaFuncSetAttribute(gemm_kernel, cudaFuncAttributeMaxDynamicSharedMemorySize,
                         SMEM_BYTES);
    cudaFuncSetAttribute(gather_kernel, cudaFuncAttributeMaxDynamicSharedMemorySize,
                         2 * FR_ * 2);

    gather_kernel<<<B_ * 8, 256, 2 * FR_ * 2>>>(video);
    wk_kernel<<<(E_ * K_ + 255) / 256, 256>>>(W);
    gemm_kernel<<<dim3(E_ / ET, M_ / (MT * TILES)), 256, SMEM_BYTES>>>(bias, pos, out);
}